// round 15
// baseline (speedup 1.0000x reference)
#include <cuda_runtime.h>
#include <math.h>

#define D  4096
#define K2 8192
#define KS 32          // split-K chunks (proven gemv shape)
#define KC (K2 / KS)   // 256 rows per chunk
#define NB 8           // n-chunks of 512 cols -> grid (8,32,4) = 1024 blocks

// ---------------- scratch (no device allocation allowed) ----------------
__device__ float    g_pre[4 * D];    // atomically-accumulated matmul results (zero-init;
                                     // each gate_tail block re-zeroes its quarter)
__device__ float    g_qa[4 * D];     // quantized gate activations
__device__ unsigned g_done;          // gate-block completion counter (zero-init)

// ---------------- helpers ----------------
__device__ __forceinline__ float mkscale(float maxabs) {
    // matches jnp.where(max_abs > 0, max_abs / 127.0, 1.0) in fp32
    return (maxabs > 0.0f) ? (maxabs / 127.0f) : 1.0f;
}
__device__ __forceinline__ float qvalr(float x, float scale, float rscale) {
    float r = rintf(x * rscale);
    r = fminf(fmaxf(r, -127.0f), 127.0f);
    return r * scale;
}
__device__ __forceinline__ float sigm(float x) {
    return __fdividef(1.0f, 1.0f + __expf(-x));
}
__device__ __forceinline__ float max4abs(float4 v) {
    return fmaxf(fmaxf(fabsf(v.x), fabsf(v.y)), fmaxf(fabsf(v.z), fabsf(v.w)));
}

// Block-wide max (signed-safe). blockDim.x multiple of 32.
__device__ __forceinline__ float blockMax(float v) {
    __shared__ float s[32];
    const unsigned full = 0xffffffffu;
    #pragma unroll
    for (int o = 16; o; o >>= 1) v = fmaxf(v, __shfl_xor_sync(full, v, o));
    int lane = threadIdx.x & 31, w = threadIdx.x >> 5;
    int nw = (blockDim.x + 31) >> 5;
    if (lane == 0) s[w] = v;
    __syncthreads();
    if (w == 0) {
        float r = (lane < nw) ? s[lane] : -INFINITY;
        #pragma unroll
        for (int o = 16; o; o >>= 1) r = fmaxf(r, __shfl_xor_sync(full, r, o));
        if (lane == 0) s[0] = r;
    }
    __syncthreads();
    float out = s[0];
    __syncthreads();
    return out;
}
// Two block maxes sharing one barrier set.
__device__ __forceinline__ float2 blockMax2(float a, float b) {
    __shared__ float sa[32], sb[32];
    const unsigned full = 0xffffffffu;
    #pragma unroll
    for (int o = 16; o; o >>= 1) {
        a = fmaxf(a, __shfl_xor_sync(full, a, o));
        b = fmaxf(b, __shfl_xor_sync(full, b, o));
    }
    int lane = threadIdx.x & 31, w = threadIdx.x >> 5;
    int nw = (blockDim.x + 31) >> 5;
    if (lane == 0) { sa[w] = a; sb[w] = b; }
    __syncthreads();
    if (w == 0) {
        float ra = (lane < nw) ? sa[lane] : -INFINITY;
        float rb = (lane < nw) ? sb[lane] : -INFINITY;
        #pragma unroll
        for (int o = 16; o; o >>= 1) {
            ra = fmaxf(ra, __shfl_xor_sync(full, ra, o));
            rb = fmaxf(rb, __shfl_xor_sync(full, rb, o));
        }
        if (lane == 0) { sa[0] = ra; sb[0] = rb; }
    }
    __syncthreads();
    float2 out = make_float2(sa[0], sb[0]);
    __syncthreads();
    return out;
}

// ---------------- kernel 1: fused concat-quant + split-K GEMV (HBM-bound) ----------------
// grid (8,32,4) x 256 thr — the proven ~76.7us shape: tiny smem, regs~32, NO post-stream
// phase. Partials accumulated with fire-and-forget RED.ADD into g_pre (R14 WIN).
__global__ void __launch_bounds__(256) gemv_kernel(
    const float* __restrict__ x,  const float* __restrict__ h,
    const float* __restrict__ Wf, const float* __restrict__ Wi,
    const float* __restrict__ Wc, const float* __restrict__ Wo)
{
    __shared__ float xs[KC];
    const int g  = blockIdx.z;
    const int kc = blockIdx.y;
    const int n0 = blockIdx.x * 512 + threadIdx.x * 2;
    const int k0 = kc * KC;
    const int t  = threadIdx.x;

    const float* W = (g == 0) ? Wf : (g == 1) ? Wi : (g == 2) ? Wc : Wo;

    // global max of |[h, x]| (identical in every block; overlapped with HBM stream)
    float lm = 0.0f;
    #pragma unroll
    for (int j = 0; j < K2 / 256; j++) {
        int i = t + j * 256;
        float v = (i < D) ? h[i] : x[i - D];
        lm = fmaxf(lm, fabsf(v));
    }
    float scale = mkscale(blockMax(lm));
    float rs = 1.0f / scale;
    {
        int gi = k0 + t;
        float v = (gi < D) ? h[gi] : x[gi - D];
        xs[t] = qvalr(v, scale, rs);
    }
    __syncthreads();

    const float2* p = reinterpret_cast<const float2*>(W + (size_t)k0 * D) + (n0 >> 1);
    const int rowstride = D / 2;
    float2 acc = make_float2(0.f, 0.f);
    #pragma unroll 8
    for (int i = 0; i < KC; i++) {
        float2 w = __ldcs(p + (size_t)i * rowstride);   // streaming: read-once weights
        float  xv = xs[i];
        acc.x = fmaf(xv, w.x, acc.x);
        acc.y = fmaf(xv, w.y, acc.y);
    }
    // fire-and-forget accumulation (RED.ADD, no return, no fence, no ticket).
    // Kernel-boundary / griddepcontrol ordering guarantees visibility downstream.
    atomicAdd(&g_pre[(size_t)g * D + n0],     acc.x);
    atomicAdd(&g_pre[(size_t)g * D + n0 + 1], acc.y);
}

// ---------------- kernel 2: gate chain (4 blocks) + fused tail in last-done block ----
// Launched with programmatic stream serialization (PDL): starts during the gemv
// drain, preloads cold b/c from DRAM, THEN griddepcontrol.wait before touching g_pre.
__global__ void __launch_bounds__(1024, 1)
gate_tail_kernel(const float* __restrict__ bf, const float* __restrict__ bi,
                 const float* __restrict__ bc, const float* __restrict__ bo,
                 const float* __restrict__ c_in, float* __restrict__ out)
{
    const int g = blockIdx.x;
    const float* b = (g == 0) ? bf : (g == 1) ? bi : (g == 2) ? bc : bo;
    const int t = threadIdx.x;

    // ---- PDL prologue: cold loads independent of gemv output ----
    float4 cv = reinterpret_cast<const float4*>(c_in)[t];
    float4 bv = reinterpret_cast<const float4*>(b)[t];

    // wait for the gemv grid to complete (makes its RED.ADDs visible)
    asm volatile("griddepcontrol.wait;" ::: "memory");

    // combined matmul result: ONE float4 load (accumulation happened in gemv)
    float4 acc = reinterpret_cast<const float4*>(g_pre)[(size_t)g * (D / 4) + t];

    // re-zero own quarter for the next graph replay (1:1 thread->element, no race)
    reinterpret_cast<float4*>(g_pre)[(size_t)g * (D / 4) + t] = make_float4(0.f, 0.f, 0.f, 0.f);

    float2 mm = blockMax2(max4abs(acc), max4abs(bv));
    float sm = mkscale(mm.x), rsm = 1.0f / sm;     // Q(x@w) scale
    float sb = mkscale(mm.y), rsb = 1.0f / sb;     // Q(b) scale

    float y[4] = { qvalr(acc.x, sm, rsm) + qvalr(bv.x, sb, rsb),
                   qvalr(acc.y, sm, rsm) + qvalr(bv.y, sb, rsb),
                   qvalr(acc.z, sm, rsm) + qvalr(bv.z, sb, rsb),
                   qvalr(acc.w, sm, rsm) + qvalr(bv.w, sb, rsb) };

    float lmax = fmaxf(fmaxf(y[0], y[1]), fmaxf(y[2], y[3]));
    float lmin = fminf(fminf(y[0], y[1]), fminf(y[2], y[3]));
    float2 ym = blockMax2(lmax, -lmin);            // (max y, -min y)
    float sy  = mkscale(fmaxf(ym.x, ym.y));
    float rsy = 1.0f / sy;

    // analytic activation scale (monotone functions -> evaluate at argmax)
    float sa;
    if (g == 2) {
        sa = mkscale(tanhf(qvalr(fmaxf(ym.x, ym.y), sy, rsy)));  // tanh odd+monotone
    } else {
        sa = mkscale(sigm(qvalr(ym.x, sy, rsy)));                // sigmoid increasing, >0
    }
    float rsa = 1.0f / sa;

    float4 qa;
    float* qp = &qa.x;
    #pragma unroll
    for (int j = 0; j < 4; j++) {
        float yq = qvalr(y[j], sy, rsy);                 // Q(Q(x@w)+Q(b))
        float a  = (g == 2) ? tanhf(yq) : sigm(yq);
        qp[j] = qvalr(a, sa, rsa);                       // Q(activation)
    }
    reinterpret_cast<float4*>(g_qa)[(size_t)g * (D / 4) + t] = qa;

    // --- last-done handshake: the 4th block to finish runs the tail inline ---
    __shared__ unsigned s_ticket;
    __threadfence();                 // release: qa visible
    __syncthreads();
    if (t == 0) s_ticket = atomicAdd(&g_done, 1u);
    __syncthreads();
    if (s_ticket != 3u) return;
    __threadfence();                 // acquire: other blocks' qa visible

    // --- tail: LSTM state update (this block only; own gate's qa in regs) ---
    const float4* qa4 = reinterpret_cast<const float4*>(g_qa);
    float4 zf = (g == 0) ? qa : qa4[0 * (D / 4) + t];
    float4 zi = (g == 1) ? qa : qa4[1 * (D / 4) + t];
    float4 z  = (g == 2) ? qa : qa4[2 * (D / 4) + t];
    float4 zo = (g == 3) ? qa : qa4[3 * (D / 4) + t];

    float mem[4] = { z.x * zi.x,  z.y * zi.y,  z.z * zi.z,  z.w * zi.w };
    float cf [4] = { cv.x * zf.x, cv.y * zf.y, cv.z * zf.z, cv.w * zf.w };

    float lm = 0.f, lc = 0.f;
    #pragma unroll
    for (int j = 0; j < 4; j++) { lm = fmaxf(lm, fabsf(mem[j])); lc = fmaxf(lc, fabsf(cf[j])); }
    float2 mc = blockMax2(lm, lc);
    float s_mem = mkscale(mc.x), r_mem = 1.0f / s_mem;
    float s_cf  = mkscale(mc.y), r_cf  = 1.0f / s_cf;

    float cn[4]; float ln = 0.f;
    #pragma unroll
    for (int j = 0; j < 4; j++) {
        cn[j] = qvalr(cf[j], s_cf, r_cf) + qvalr(mem[j], s_mem, r_mem);  // Q(c*zf)+Q(z*zi)
        ln = fmaxf(ln, fabsf(cn[j]));
    }
    float cnmax = blockMax(ln);
    float s_cn  = mkscale(cnmax), r_cn = 1.0f / s_cn;

    // analytic: max|tanh(Q(cn))| = tanh(Q(max|cn|))
    float s_t = mkscale(tanhf(qvalr(cnmax, s_cn, r_cn)));
    float r_t = 1.0f / s_t;

    float zop[4] = { zo.x, zo.y, zo.z, zo.w };
    float hv[4]; float lh = 0.f;
    #pragma unroll
    for (int j = 0; j < 4; j++) {
        float cq = qvalr(cn[j], s_cn, r_cn);             // c_new
        float tq = qvalr(tanhf(cq), s_t, r_t);           // Q(tanh(c_new))
        hv[j] = zop[j] * tq;
        lh = fmaxf(lh, fabsf(hv[j]));
    }
    float s_h = mkscale(blockMax(lh)), r_h = 1.0f / s_h;

    float4 o;
    o.x = qvalr(hv[0], s_h, r_h); o.y = qvalr(hv[1], s_h, r_h);
    o.z = qvalr(hv[2], s_h, r_h); o.w = qvalr(hv[3], s_h, r_h);
    reinterpret_cast<float4*>(out)[t] = o;

    // reset handshake for the next graph replay (only this block is alive here)
    __syncthreads();
    if (t == 0) g_done = 0u;
    __threadfence();
}

// ---------------- launch ----------------
extern "C" void kernel_launch(void* const* d_in, const int* in_sizes, int n_in,
                              void* d_out, int out_size)
{
    const float* x  = (const float*)d_in[0];
    const float* c  = (const float*)d_in[1];
    const float* h  = (const float*)d_in[2];
    const float* Wf = (const float*)d_in[3];
    const float* bf = (const float*)d_in[4];
    const float* Wi = (const float*)d_in[5];
    const float* bi = (const float*)d_in[6];
    const float* Wc = (const float*)d_in[7];
    const float* bc = (const float*)d_in[8];
    const float* Wo = (const float*)d_in[9];
    const float* bo = (const float*)d_in[10];
    float* out = (float*)d_out;

    dim3 gridB(NB, KS, 4);                     // (8, 32, 4) = 1024 blocks
    gemv_kernel<<<gridB, 256>>>(x, h, Wf, Wi, Wc, Wo);

    // PDL launch: gate_tail may start during the gemv drain; it preloads b/c,
    // then griddepcontrol.wait gates the g_pre reads on gemv completion.
    cudaLaunchConfig_t cfg = {};
    cfg.gridDim  = dim3(4, 1, 1);
    cfg.blockDim = dim3(1024, 1, 1);
    cfg.dynamicSmemBytes = 0;
    cfg.stream = 0;
    cudaLaunchAttribute attrs[1];
    attrs[0].id = cudaLaunchAttributeProgrammaticStreamSerialization;
    attrs[0].val.programmaticStreamSerializationAllowed = 1;
    cfg.attrs = attrs;
    cfg.numAttrs = 1;
    cudaLaunchKernelEx(&cfg, gate_tail_kernel, bf, bi, bc, bo, c, out);
}